// round 14
// baseline (speedup 1.0000x reference)
#include <cuda_runtime.h>

// Fused depth-3 sliding-window path signature (Chen chunk factorization),
// shuffle-compressed scan state (64 regs) + fine grid (9 groups/batch) for
// 16 blocks/SM single-wave residency.
// B=256, L=2048, C=6, WIN=64, STRIDE=32 -> 63 windows / batch.
// Grid = 2304 blocks (batch = blk/9, group g = blk%9) x 64 threads.
// Scan lane (chunk, i): s1, T2[j]=3*(2*s2[i][j]), and only the 21 level-3
// components S3[i][j][k] (=6*s3) with j<=k; the 15 with j>k reconstructed
// post-scan from the shuffle identities (verified in R11):
//   s1[k]s2[i][j] = s3[k][i][j]+s3[i][k][j]+s3[i][j][k]   (i<=j, i!=k)
//   s1[i]s2[j][i] = s3[i][j][i]+2 s3[j][i][i]             (i==k)
//   s3[i][j][k]   = s1[i]s2[j][k]-s1[k]s2[j][i]+s3[k][j][i]  (i>j)

namespace {

constexpr int BATCH   = 256;
constexpr int LEN     = 2048;
constexpr int CH      = 6;
constexpr int NW      = 63;
constexpr int GROUPS  = 9;
constexpr int THREADS = 64;
constexpr int NCHUNKL = 8;                // chunks per block (1 overlap)
constexpr int NWL     = 7;                // windows per block (9*7 = 63 exact)
constexpr int NDXL    = 256;              // staged increments per block
constexpr int SROWD2  = 265;              // float2 row stride (256 + 8 pad, odd)
constexpr int NLANE   = NCHUNKL * CH;     // 48 scan lanes
constexpr int SCOL    = 49;               // sig column stride (48 + 1)
constexpr int SM_FLOATS = 43 * SCOL;      // 2107 >= max(3*265*2=1590, 7*258=1806)

__global__ __launch_bounds__(THREADS, 16)
void fused_kernel(const float* __restrict__ path, float* __restrict__ out) {
    __shared__ __align__(16) float sm[SM_FLOATS];
    float2* __restrict__ s_dx2 = reinterpret_cast<float2*>(sm); // [3][SROWD2]
    float*  __restrict__ s_sig = sm;                            // [43][SCOL]

    const int tid = threadIdx.x;
    const int b   = blockIdx.x / GROUPS;
    const int g   = blockIdx.x - b * GROUPS;
    const int l0  = g * (NWL * 32);                 // 224 * g
    const float2* __restrict__ rowv =
        reinterpret_cast<const float2*>(path + (long long)b * (LEN * CH));

    // ---- stage increments as float2 (zero-fill global l >= 2047) ----
    for (int idx = tid; idx < NDXL * 3; idx += THREADS) {
        const int l  = idx / 3;
        const int pr = idx - l * 3;
        float2 d2 = make_float2(0.0f, 0.0f);
        const int gl = l0 + l;
        if (gl < LEN - 1) {
            const float2 v0 = rowv[gl * 3 + pr];
            const float2 v1 = rowv[gl * 3 + 3 + pr];
            d2.x = v1.x - v0.x;
            d2.y = v1.y - v0.y;
        }
        s_dx2[pr * SROWD2 + l + (l >> 5)] = d2;
    }
    __syncthreads();

    const int mc = tid / CH;       // local chunk 0..7 (tid>=48: idle lanes)
    const int i  = tid - mc * CH;  // leading channel
    const bool scan_lane = (tid < NLANE);

    float s1 = 0.0f;
    float T2[6];                   // 3 * S2  (S2 = 2*s2)
    float K3[6][6];                // kept S3[i][j][k], j<=k only (upper tri)
#pragma unroll
    for (int j = 0; j < 6; ++j) {
        T2[j] = 0.0f;
#pragma unroll
        for (int k = j; k < 6; ++k) K3[j][k] = 0.0f;
    }

    if (scan_lane) {
        const int base = 33 * mc;  // padded float2 offset of local l = 32*mc
        const float* __restrict__ rowi = sm + 2 * (i >> 1) * SROWD2 + (i & 1);

#pragma unroll 4
        for (int t = 0; t < 32; ++t) {
            const int off = base + t;
            const float2 d01 = s_dx2[0 * SROWD2 + off];
            const float2 d23 = s_dx2[1 * SROWD2 + off];
            const float2 d45 = s_dx2[2 * SROWD2 + off];
            const float di = rowi[2 * off];

            const float a   = fmaf(3.0f, s1, di);          // di + 3 s1 (old s1)
            const float b23 = fmaf(6.0f, s1, 3.0f * di);   // 3*(di + 2 s1)

            const float d[6] = {d01.x, d01.y, d23.x, d23.y, d45.x, d45.y};

            float coef[6];                                  // uses old T2
#pragma unroll
            for (int j = 0; j < 6; ++j) coef[j] = fmaf(a, d[j], T2[j]);

#pragma unroll
            for (int j = 0; j < 6; ++j)
#pragma unroll
                for (int k = j; k < 6; ++k)                 // kept 21 only
                    K3[j][k] = fmaf(coef[j], d[k], K3[j][k]);

#pragma unroll
            for (int j = 0; j < 6; ++j) T2[j] = fmaf(b23, d[j], T2[j]);
            s1 += di;
        }
    }

    // ---- snapshot d_last for local window wl = mc (local l' = 32mc+63) ----
    float dc[6];
    {
        const int off = 33 * mc + 64;
        const bool cwn = (mc < NWL);
        float2 c01 = make_float2(0.0f, 0.0f), c23 = c01, c45 = c01;
        if (cwn) {
            c01 = s_dx2[0 * SROWD2 + off];
            c23 = s_dx2[1 * SROWD2 + off];
            c45 = s_dx2[2 * SROWD2 + off];
        }
        dc[0] = c01.x; dc[1] = c01.y; dc[2] = c23.x;
        dc[3] = c23.y; dc[4] = c45.x; dc[5] = c45.y;
    }
    __syncthreads();   // all dx reads done before s_sig overwrites

    // ---- publish s1, S2 = T2/3, and the 21 kept S3 components ----
    if (scan_lane) {
        s_sig[tid] = s1;
        const float third = 1.0f / 3.0f;
#pragma unroll
        for (int j = 0; j < 6; ++j) s_sig[(1 + j) * SCOL + tid] = T2[j] * third;
#pragma unroll
        for (int j = 0; j < 6; ++j)
#pragma unroll
            for (int k = j; k < 6; ++k)
                s_sig[(7 + j * 6 + k) * SCOL + tid] = K3[j][k];
    }
    __syncthreads();

    // ---- reconstruct the 15 components with j > k via shuffle identities ----
    if (scan_lane) {
        const int col0 = tid - i;               // column of lane 0 of this chunk
        float s1v[6];
#pragma unroll
        for (int x = 0; x < 6; ++x) s1v[x] = s_sig[col0 + x];

#pragma unroll
        for (int j = 1; j < 6; ++j) {
#pragma unroll
            for (int k = 0; k < j; ++k) {
                float U;
                if (i == k) {
                    // S3[i][j][i] = 3 s1 S2[j][i] - 2 S3[j][i][i]
                    U = 3.0f * s1 * s_sig[(1 + i) * SCOL + col0 + j]
                      - 2.0f * s_sig[(7 + i * 6 + i) * SCOL + col0 + j];
                } else if (i > j) {
                    // S3[i][j][k] = 3 s1 S2[j][k] - 3 s1[k] S2[j][i] + S3[k][j][i]
                    U = 3.0f * s1 * s_sig[(1 + k) * SCOL + col0 + j]
                      - 3.0f * s1v[k] * s_sig[(1 + i) * SCOL + col0 + j]
                      + s_sig[(7 + j * 6 + i) * SCOL + col0 + k];
                } else {
                    // i <= j, i != k:
                    // S3[i][j][k] = s1[k]*T2[j] - S3[k][i][j] - S3[i][k][j]
                    U = s1v[k] * T2[j]
                      - s_sig[(7 + i * 6 + j) * SCOL + col0 + k]
                      - K3[k][j];
                }
                s_sig[(7 + j * 6 + k) * SCOL + tid] = U;
            }
        }
    }
    __syncthreads();

    // ---- combine into registers: window w = 7g + mc ----
    const bool cw = (mc < NWL);    // w = 7g + mc <= 7*8+6 = 62 < NW always

    float r1 = 0.0f, r2[6], r3[6][6];
    if (cw) {
        const int ca  = tid;               // A_w lane i
        const int cb0 = (mc + 1) * CH;     // A_{w+1} lane base
        const int cbi = cb0 + i;

        const float a1 = s_sig[ca];
        float b1[6];
#pragma unroll
        for (int j = 0; j < 6; ++j) b1[j] = s_sig[cb0 + j];

        const float m1 = a1 + b1[i];

        // M2 row i (2x): M2[j] = A2[i][j] + B2[i][j] + 2 a1 b1[j]
        float A2r[6], M2[6];
#pragma unroll
        for (int j = 0; j < 6; ++j) {
            A2r[j] = s_sig[(1 + j) * SCOL + ca];
            M2[j]  = A2r[j] + s_sig[(1 + j) * SCOL + cbi] + 2.0f * a1 * b1[j];
        }

        r1 = m1 - dc[i];

        const float c2 = dc[i] - 2.0f * m1;
#pragma unroll
        for (int j = 0; j < 6; ++j) r2[j] = fmaf(c2, dc[j], M2[j]);

        const float t3a1 = 3.0f * a1;
        const float c3   = 3.0f * m1 - dc[i];
#pragma unroll
        for (int j = 0; j < 6; ++j) {
            const float a2b  = 3.0f * A2r[j];
            const float coef = fmaf(c3, dc[j], -3.0f * M2[j]);
#pragma unroll
            for (int k = 0; k < 6; ++k) {
                float v = s_sig[(7 + j * 6 + k) * SCOL + ca]
                        + s_sig[(7 + j * 6 + k) * SCOL + cbi];
                v = fmaf(a2b, b1[k], v);
                v = fmaf(t3a1, s_sig[(1 + k) * SCOL + cb0 + j], v);
                r3[j][k] = fmaf(coef, dc[k], v);
            }
        }
    }
    __syncthreads();   // all s_sig reads done before output staging overwrites

    // ---- stage output in smem as [wl][258] ----
    if (cw) {
        float* __restrict__ so = sm + mc * 258;
        so[i] = r1;
#pragma unroll
        for (int j = 0; j < 6; ++j) so[6 + i * 6 + j] = r2[j];
#pragma unroll
        for (int j = 0; j < 6; ++j)
#pragma unroll
            for (int k = 0; k < 6; ++k) so[42 + i * 36 + j * 6 + k] = r3[j][k];
    }
    __syncthreads();

    // ---- float2-coalesced copy to global (7*258 = 1806 floats = 903 f2) ----
    constexpr int CNT2 = NWL * 258 / 2;  // 903
    const float2* __restrict__ ssrc = reinterpret_cast<const float2*>(sm);
    float2* __restrict__ gout = reinterpret_cast<float2*>(
        out + ((long long)b * NW + NWL * g) * 258);
    for (int idx = tid; idx < CNT2; idx += THREADS) gout[idx] = ssrc[idx];
}

}  // namespace

extern "C" void kernel_launch(void* const* d_in, const int* in_sizes, int n_in,
                              void* d_out, int out_size) {
    const float* path = (const float*)d_in[0];
    float* out = (float*)d_out;
    fused_kernel<<<BATCH * GROUPS, THREADS>>>(path, out);
}